// round 13
// baseline (speedup 1.0000x reference)
#include <cuda_runtime.h>
#include <cuda_bf16.h>
#include <math.h>
#include <stdint.h>

#define N_NODES 100000
#define DIM     128
#define N_REL   8
#define N_EDGES 640000
#define TILE_M  64
#define MAX_TILES_PER_TYPE 1400          // 89600 edges/type capacity (mean 80K)

// ---------------- scratch (static device globals; no allocation) -------------
__device__ float g_deg  [N_NODES];
__device__ int   g_tcur [N_REL];         // bucket cursor; == count after fill
__device__ int   g_erow [N_REL * 89600];
__device__ int   g_ecol [N_REL * 89600];
__device__ float g_ecoef[N_REL * 89600];
__device__ float g_agg  [(size_t)N_NODES * DIM];
__device__ float g_z1   [(size_t)N_NODES * DIM];
// prepacked, transposed (W^T: [r][j=out][k=in]) bf16 hi/lo weight images
__device__ uint4 g_B1h[16384];   // 8 rel * 32768 B each
__device__ uint4 g_B1l[16384];
__device__ uint4 g_B2h[16384];
__device__ uint4 g_B2l[16384];

#define BUCKET_STRIDE 89600

// ===================== helpers ===============================================
__device__ __forceinline__ uint32_t smem_u32(const void* p) {
    uint32_t a;
    asm("{ .reg .u64 t; cvta.to.shared.u64 t, %1; cvt.u32.u64 %0, t; }" : "=r"(a) : "l"(p));
    return a;
}

__device__ __forceinline__ void split4(float4 v, uint2& hi, uint2& lo) {
    __nv_bfloat16 h0 = __float2bfloat16(v.x), h1 = __float2bfloat16(v.y);
    __nv_bfloat16 h2 = __float2bfloat16(v.z), h3 = __float2bfloat16(v.w);
    __nv_bfloat16 l0 = __float2bfloat16(v.x - __bfloat162float(h0));
    __nv_bfloat16 l1 = __float2bfloat16(v.y - __bfloat162float(h1));
    __nv_bfloat16 l2 = __float2bfloat16(v.z - __bfloat162float(h2));
    __nv_bfloat16 l3 = __float2bfloat16(v.w - __bfloat162float(h3));
    hi.x = (uint32_t)__bfloat16_as_ushort(h0) | ((uint32_t)__bfloat16_as_ushort(h1) << 16);
    hi.y = (uint32_t)__bfloat16_as_ushort(h2) | ((uint32_t)__bfloat16_as_ushort(h3) << 16);
    lo.x = (uint32_t)__bfloat16_as_ushort(l0) | ((uint32_t)__bfloat16_as_ushort(l1) << 16);
    lo.y = (uint32_t)__bfloat16_as_ushort(l2) | ((uint32_t)__bfloat16_as_ushort(l3) << 16);
}

#define LDSM_X4(r0, r1, r2, r3, addr) \
    asm volatile("ldmatrix.sync.aligned.m8n8.x4.shared.b16 {%0,%1,%2,%3}, [%4];" \
                 : "=r"(r0), "=r"(r1), "=r"(r2), "=r"(r3) : "r"(addr))

#define MMA16816(c, a0, a1, a2, a3, b0, b1) \
    asm volatile("mma.sync.aligned.m16n8k16.row.col.f32.bf16.bf16.f32 " \
                 "{%0,%1,%2,%3}, {%4,%5,%6,%7}, {%8,%9}, {%0,%1,%2,%3};" \
                 : "+f"((c)[0]), "+f"((c)[1]), "+f"((c)[2]), "+f"((c)[3]) \
                 : "r"(a0), "r"(a1), "r"(a2), "r"(a3), "r"(b0), "r"(b1))

#define CP_ASYNC16(dst, src) \
    asm volatile("cp.async.ca.shared.global [%0], [%1], 16;" :: "r"(dst), "l"(src) : "memory")
#define CP_COMMIT() asm volatile("cp.async.commit_group;" ::: "memory")

// ---------------- fused zero + weight prepack --------------------------------
static constexpr int ZERO_F4 = 3200000 + 25000;          // agg + deg as float4
static constexpr int ZB = (ZERO_F4 + 1 + 255) / 256;     // 12599

__global__ void zero_prepack_kernel(const float* __restrict__ W1,
                                    const float* __restrict__ W2,
                                    unsigned char* __restrict__ o1h,
                                    unsigned char* __restrict__ o1l,
                                    unsigned char* __restrict__ o2h,
                                    unsigned char* __restrict__ o2l) {
    int b = blockIdx.x;
    if (b < ZB) {
        int i = b * 256 + threadIdx.x;
        const float4 z4 = make_float4(0.f, 0.f, 0.f, 0.f);
        if (i < 3200000)        ((float4*)g_agg)[i] = z4;
        else if (i < ZERO_F4)   ((float4*)g_deg)[i - 3200000] = z4;
        else if (i == ZERO_F4) {
            #pragma unroll
            for (int t = 0; t < N_REL; t++) g_tcur[t] = 0;
        }
        return;
    }
    int t = (b - ZB) * 256 + threadIdx.x;       // 0..65535
    const float* W = (t < 32768) ? W1 : W2;
    unsigned char* oh = (t < 32768) ? o1h : o2h;
    unsigned char* ol = (t < 32768) ? o1l : o2l;
    int u  = t & 32767;
    int r  = u >> 12;
    int j  = (u >> 5) & 127;
    int k  = (u & 31) * 4;
    const float* Wr = W + r * 16384;
    float4 v = make_float4(Wr[(k + 0) * 128 + j], Wr[(k + 1) * 128 + j],
                           Wr[(k + 2) * 128 + j], Wr[(k + 3) * 128 + j]);
    uint2 hi, lo;
    split4(v, hi, lo);
    uint32_t off = (uint32_t)r * 32768u + (uint32_t)j * 256u + (uint32_t)k * 2u;
    *(uint2*)(oh + off) = hi;
    *(uint2*)(ol + off) = lo;
}

// ---------------- degree histogram -------------------------------------------
__global__ void hist_kernel(const int* __restrict__ col) {
    int e = blockIdx.x * 256 + threadIdx.x;
    if (e < N_EDGES) atomicAdd(&g_deg[col[e]], 1.0f);
}

// ---------------- bucket fill (inline norm coefficients) ---------------------
__global__ void fill_kernel(const int* __restrict__ row,
                            const int* __restrict__ col,
                            const int* __restrict__ etype,
                            const float* __restrict__ ew) {
    int e = blockIdx.x * 256 + threadIdx.x;
    if (e >= N_EDGES) return;
    int r = row[e], c = col[e], t = etype[e];
    float dr = g_deg[r], dc = g_deg[c];
    float ir = (dr > 0.0f) ? rsqrtf(dr) : 0.0f;
    float cf = ir * rsqrtf(dc) * ew[e];          // dc >= 1 (this edge targets c)
    int p = atomicAdd(&g_tcur[t], 1);
    int gi = t * BUCKET_STRIDE + p;
    g_erow [gi] = r;
    g_ecol [gi] = c;
    g_ecoef[gi] = cf;
}

// ---------------- edge-batched GEMM: agg[col] += coef * (x[row] @ W_t) -------
// 64-edge x 64-out-col half-tiles, 256 threads, 3 CTAs/SM.
static constexpr int S_ELEM = 136;
static constexpr int S_BYTE = S_ELEM * 2;              // 272
static constexpr int A_TILE = TILE_M * S_BYTE;         // 17408
static constexpr int B_HALF = 64 * S_BYTE;             // 17408
static constexpr int OFF_A_HI = 0;
static constexpr int OFF_A_LO = A_TILE;                // 17408
static constexpr int OFF_B_HI = 2 * A_TILE;            // 34816
static constexpr int OFF_B_LO = OFF_B_HI + B_HALF;     // 52224
static constexpr int OFF_COL  = OFF_B_LO + B_HALF;     // 69632
static constexpr int OFF_COEF = OFF_COL + 256;         // 69888
static constexpr int OFF_ROW  = OFF_COEF + 256;        // 70144
static constexpr int SMEM_BYTES = OFF_ROW + 256;       // 70400
static constexpr int STAGE_STRIDE = 68;                // floats; 64*68*4 = 17408 = A region

__global__ __launch_bounds__(256, 3)
void egemm_kernel(const float* __restrict__ A,
                  const uint4* __restrict__ Bh,
                  const uint4* __restrict__ Bl) {
    extern __shared__ unsigned char smem[];
    const uint32_t sb = smem_u32(smem);
    const int tid    = threadIdx.x;
    const int wid    = tid >> 5;
    const int lane   = tid & 31;
    const int warp_m = wid & 1;          // 2 tiles of 32 rows
    const int warp_n = wid >> 1;         // 4 tiles of 16 cols

    const int t   = blockIdx.y;
    const int nh  = blockIdx.z;          // output-col half: cols [nh*64, nh*64+64)
    const int cnt = g_tcur[t];
    const int ntiles = (cnt + TILE_M - 1) / TILE_M;
    if ((int)blockIdx.x >= ntiles) return;
    const int ebase = blockIdx.x * TILE_M;

    // ---- B half load (cp.async; W_t prepacked, L2-resident) ----------------
    {
        uint32_t dstH = sb + OFF_B_HI, dstL = sb + OFF_B_LO;
        const char* srcH = (const char*)Bh + (size_t)t * 32768 + (size_t)nh * 16384;
        const char* srcL = (const char*)Bl + (size_t)t * 32768 + (size_t)nh * 16384;
        #pragma unroll
        for (int q = 0; q < 4; q++) {
            int i   = tid + q * 256;       // 0..1023 chunks of 16B
            int j   = i >> 4;              // local out col 0..63
            int k16 = i & 15;
            uint32_t doff = (uint32_t)j * S_BYTE + k16 * 16;
            uint32_t soff = (uint32_t)j * 256 + k16 * 16;
            CP_ASYNC16(dstH + doff, srcH + soff);
            CP_ASYNC16(dstL + doff, srcL + soff);
        }
        CP_COMMIT();
    }

    // edge metadata for this tile (validity folded into coef)
    if (tid < TILE_M) {
        int i = ebase + tid;
        bool v = (i < cnt);
        int gi = t * BUCKET_STRIDE + (v ? i : 0);
        ((int*)  (smem + OFF_ROW ))[tid] = v ? g_erow[gi] : 0;
        ((int*)  (smem + OFF_COL ))[tid] = v ? g_ecol[gi] : 0;
        ((float*)(smem + OFF_COEF))[tid] = v ? g_ecoef[gi] : 0.0f;
    }
    __syncthreads();

    // gather source rows + bf16 hi/lo split into padded SMEM
    {
        const int* rowbuf = (const int*)(smem + OFF_ROW);
        const int cg    = tid & 31;
        const int rbase = tid >> 5;      // 0..7
        #pragma unroll
        for (int i = 0; i < 8; i++) {
            int row  = rbase + i * 8;
            int srow = rowbuf[row];
            float4 v = ((const float4*)A)[(size_t)srow * 32 + cg];
            uint2 hi, lo;
            split4(v, hi, lo);
            uint32_t off = (uint32_t)row * S_BYTE + (uint32_t)cg * 8;
            *(uint2*)(smem + OFF_A_HI + off) = hi;
            *(uint2*)(smem + OFF_A_LO + off) = lo;
        }
    }
    asm volatile("cp.async.wait_group 0;" ::: "memory");
    __syncthreads();

    // ldmatrix fragment addresses
    const int lr = lane & 15;
    const int lc = lane >> 4;
    uint32_t aRow[2];
    #pragma unroll
    for (int mt = 0; mt < 2; mt++)
        aRow[mt] = (uint32_t)(warp_m * 32 + mt * 16 + lr) * S_BYTE + lc * 16;
    const uint32_t bRow = (uint32_t)(warp_n * 16 + lr) * S_BYTE + lc * 16;

    float c[2][2][4];
    #pragma unroll
    for (int mt = 0; mt < 2; mt++)
        #pragma unroll
        for (int nt = 0; nt < 2; nt++)
            #pragma unroll
            for (int e = 0; e < 4; e++) c[mt][nt][e] = 0.0f;

    const uint32_t bStageH = sb + OFF_B_HI;
    const uint32_t bStageL = sb + OFF_B_LO;
    const uint32_t aBaseH  = sb + OFF_A_HI;
    const uint32_t aBaseL  = sb + OFF_A_LO;

    uint32_t ah[2][2][4], al[2][2][4], bh[2][4], bl[2][4];

    #define LOAD_FRAG(buf, kb)                                                   \
        do {                                                                     \
            _Pragma("unroll")                                                    \
            for (int mt = 0; mt < 2; mt++) {                                     \
                LDSM_X4(ah[buf][mt][0], ah[buf][mt][1], ah[buf][mt][2],          \
                        ah[buf][mt][3], aBaseH + aRow[mt] + (kb));               \
                LDSM_X4(al[buf][mt][0], al[buf][mt][1], al[buf][mt][2],          \
                        al[buf][mt][3], aBaseL + aRow[mt] + (kb));               \
            }                                                                    \
            LDSM_X4(bh[buf][0], bh[buf][1], bh[buf][2], bh[buf][3],              \
                    bStageH + bRow + (kb));                                      \
            LDSM_X4(bl[buf][0], bl[buf][1], bl[buf][2], bl[buf][3],              \
                    bStageL + bRow + (kb));                                      \
        } while (0)

    LOAD_FRAG(0, 0);
    #pragma unroll
    for (int ks = 0; ks < 8; ks++) {
        const int cur = ks & 1;
        if (ks < 7) LOAD_FRAG(cur ^ 1, (ks + 1) * 32);
        // c += Ah@Bh + Ah@Bl + Al@Bh (Al@Bl dropped, ~2^-18 relative)
        #pragma unroll
        for (int mt = 0; mt < 2; mt++) {
            MMA16816(c[mt][0], ah[cur][mt][0], ah[cur][mt][1],
                     ah[cur][mt][2], ah[cur][mt][3], bh[cur][0], bh[cur][2]);
            MMA16816(c[mt][1], ah[cur][mt][0], ah[cur][mt][1],
                     ah[cur][mt][2], ah[cur][mt][3], bh[cur][1], bh[cur][3]);
            MMA16816(c[mt][0], ah[cur][mt][0], ah[cur][mt][1],
                     ah[cur][mt][2], ah[cur][mt][3], bl[cur][0], bl[cur][2]);
            MMA16816(c[mt][1], ah[cur][mt][0], ah[cur][mt][1],
                     ah[cur][mt][2], ah[cur][mt][3], bl[cur][1], bl[cur][3]);
            MMA16816(c[mt][0], al[cur][mt][0], al[cur][mt][1],
                     al[cur][mt][2], al[cur][mt][3], bh[cur][0], bh[cur][2]);
            MMA16816(c[mt][1], al[cur][mt][0], al[cur][mt][1],
                     al[cur][mt][2], al[cur][mt][3], bh[cur][1], bh[cur][3]);
        }
    }
    #undef LOAD_FRAG

    __syncthreads();   // A-region reads done; safe to overwrite with stage

    // stage 64x64 message half-tile to SMEM (row-major, padded stride)
    float* stage = (float*)smem;
    const int gid = lane >> 2;
    const int tig = lane & 3;
    #pragma unroll
    for (int mt = 0; mt < 2; mt++) {
        int rA = warp_m * 32 + mt * 16 + gid;
        int rB = rA + 8;
        #pragma unroll
        for (int nt = 0; nt < 2; nt++) {
            int d = warp_n * 16 + nt * 8 + 2 * tig;
            stage[rA * STAGE_STRIDE + d]     = c[mt][nt][0];
            stage[rA * STAGE_STRIDE + d + 1] = c[mt][nt][1];
            stage[rB * STAGE_STRIDE + d]     = c[mt][nt][2];
            stage[rB * STAGE_STRIDE + d + 1] = c[mt][nt][3];
        }
    }
    __syncthreads();

    // coalesced vector-RED into agg[col] (L2-resident, 51 MB footprint)
    // 2 rows per warp-iteration: lanes 0-15 row A, lanes 16-31 row B
    const float* coefbuf = (const float*)(smem + OFF_COEF);
    const int*   colbuf  = (const int*)  (smem + OFF_COL);
    const int sub = lane & 15;
    #pragma unroll
    for (int i = 0; i < 4; i++) {
        int row  = wid * 8 + i * 2 + (lane >> 4);
        float cf = coefbuf[row];
        if (cf != 0.0f) {
            int cn = colbuf[row];
            float4 v = *(const float4*)&stage[row * STAGE_STRIDE + sub * 4];
            float* dst = &g_agg[(size_t)cn * DIM + nh * 64 + sub * 4];
            asm volatile("red.global.add.v4.f32 [%0], {%1, %2, %3, %4};"
                         :: "l"(dst), "f"(cf * v.x), "f"(cf * v.y),
                            "f"(cf * v.z), "f"(cf * v.w)
                         : "memory");
        }
    }
}

// ---------------- bias + relu -> z1, re-zero agg for conv2 --------------------
__global__ void bias_relu_zero_kernel(const float* __restrict__ b1) {
    int i = blockIdx.x * blockDim.x + threadIdx.x;       // float4 index
    if (i < N_NODES * DIM / 4) {
        float4 a = ((const float4*)g_agg)[i];
        const float4 b = ((const float4*)b1)[i & 31];
        float4 o;
        o.x = fmaxf(a.x + b.x, 0.f);
        o.y = fmaxf(a.y + b.y, 0.f);
        o.z = fmaxf(a.z + b.z, 0.f);
        o.w = fmaxf(a.w + b.w, 0.f);
        ((float4*)g_z1)[i] = o;
        ((float4*)g_agg)[i] = make_float4(0.f, 0.f, 0.f, 0.f);
    }
}

// ---------------- final combine ----------------------------------------------
__global__ void final_kernel(const float* __restrict__ x,
                             const float* __restrict__ b2,
                             float* __restrict__ out) {
    int i = blockIdx.x * blockDim.x + threadIdx.x;       // float4 index
    if (i < N_NODES * DIM / 4) {
        float4 a  = ((const float4*)g_agg)[i];
        float4 b  = ((const float4*)b2)[i & 31];
        float4 z1 = ((const float4*)g_z1)[i];
        float4 xv = ((const float4*)x)[i];
        float4 st, sh;
        st.x = (xv.x + z1.x + a.x + b.x) * 0.25f;  sh.x = (z1.x + a.x + b.x) * (1.f / 3.f);
        st.y = (xv.y + z1.y + a.y + b.y) * 0.25f;  sh.y = (z1.y + a.y + b.y) * (1.f / 3.f);
        st.z = (xv.z + z1.z + a.z + b.z) * 0.25f;  sh.z = (z1.z + a.z + b.z) * (1.f / 3.f);
        st.w = (xv.w + z1.w + a.w + b.w) * 0.25f;  sh.w = (z1.w + a.w + b.w) * (1.f / 3.f);
        ((float4*)out)[i] = st;
        ((float4*)out)[(size_t)N_NODES * DIM / 4 + i] = sh;
    }
}

// ---------------- launch -----------------------------------------------------
extern "C" void kernel_launch(void* const* d_in, const int* in_sizes, int n_in,
                              void* d_out, int out_size) {
    const float* x  = (const float*)d_in[0];
    const int*   ei = (const int*)  d_in[1];
    const int*   et = (const int*)  d_in[2];
    const float* ew = (const float*)d_in[3];
    const float* W1 = (const float*)d_in[4];
    const float* b1 = (const float*)d_in[5];
    const float* W2 = (const float*)d_in[6];
    const float* b2 = (const float*)d_in[7];
    float* out = (float*)d_out;

    const int* row = ei;
    const int* col = ei + N_EDGES;

    void *p_z1, *p_B1h, *p_B1l, *p_B2h, *p_B2l;
    cudaGetSymbolAddress(&p_z1,  g_z1);
    cudaGetSymbolAddress(&p_B1h, g_B1h);
    cudaGetSymbolAddress(&p_B1l, g_B1l);
    cudaGetSymbolAddress(&p_B2h, g_B2h);
    cudaGetSymbolAddress(&p_B2l, g_B2l);

    cudaFuncSetAttribute(egemm_kernel, cudaFuncAttributeMaxDynamicSharedMemorySize, SMEM_BYTES);

    const int EB = (N_EDGES + 255) / 256;
    const int V4 = (N_NODES * DIM / 4 + 255) / 256;
    dim3 egrid(MAX_TILES_PER_TYPE, N_REL, 2);

    zero_prepack_kernel<<<ZB + 256, 256>>>(W1, W2,
                                 (unsigned char*)p_B1h, (unsigned char*)p_B1l,
                                 (unsigned char*)p_B2h, (unsigned char*)p_B2l); // [0]
    hist_kernel<<<EB, 256>>>(col);                                         // [1]
    fill_kernel<<<EB, 256>>>(row, col, et, ew);                            // [2]

    // conv 1: agg += coef * (x[row] @ W1[t]) scattered to col
    egemm_kernel<<<egrid, 256, SMEM_BYTES>>>(x, (const uint4*)p_B1h,
                                             (const uint4*)p_B1l);         // [3] <- ncu
    bias_relu_zero_kernel<<<V4, 256>>>(b1);                                // [4]

    // conv 2: agg += coef * (z1[row] @ W2[t]) scattered to col
    egemm_kernel<<<egrid, 256, SMEM_BYTES>>>((const float*)p_z1,
                                             (const uint4*)p_B2h,
                                             (const uint4*)p_B2l);         // [5]
    final_kernel<<<V4, 256>>>(x, b2, out);                                 // [6]
}

// round 14
// speedup vs baseline: 1.1478x; 1.1478x over previous
#include <cuda_runtime.h>
#include <cuda_bf16.h>
#include <math.h>
#include <stdint.h>

#define N_NODES 100000
#define DIM     128
#define N_REL   8
#define N_EDGES 640000
#define TILE_M  64
#define MAX_TILES_PER_TYPE 1400          // 89600 edges/type capacity (mean 80K)

// ---------------- scratch (static device globals; no allocation) -------------
__device__ float g_deg  [N_NODES];
__device__ int   g_tcur [N_REL];         // bucket cursor; == count after fill
__device__ int   g_erow [N_REL * 89600];
__device__ int   g_ecol [N_REL * 89600];
__device__ float g_ecoef[N_REL * 89600];
__device__ float g_agg  [(size_t)N_NODES * DIM];
__device__ float g_z1   [(size_t)N_NODES * DIM];
// prepacked, transposed (W^T: [r][j=out][k=in]) bf16 hi/lo weight images
__device__ uint4 g_B1h[16384];   // 8 rel * 32768 B each
__device__ uint4 g_B1l[16384];
__device__ uint4 g_B2h[16384];
__device__ uint4 g_B2l[16384];

#define BUCKET_STRIDE 89600

// ===================== helpers ===============================================
__device__ __forceinline__ uint32_t smem_u32(const void* p) {
    uint32_t a;
    asm("{ .reg .u64 t; cvta.to.shared.u64 t, %1; cvt.u32.u64 %0, t; }" : "=r"(a) : "l"(p));
    return a;
}

__device__ __forceinline__ void split4(float4 v, uint2& hi, uint2& lo) {
    __nv_bfloat16 h0 = __float2bfloat16(v.x), h1 = __float2bfloat16(v.y);
    __nv_bfloat16 h2 = __float2bfloat16(v.z), h3 = __float2bfloat16(v.w);
    __nv_bfloat16 l0 = __float2bfloat16(v.x - __bfloat162float(h0));
    __nv_bfloat16 l1 = __float2bfloat16(v.y - __bfloat162float(h1));
    __nv_bfloat16 l2 = __float2bfloat16(v.z - __bfloat162float(h2));
    __nv_bfloat16 l3 = __float2bfloat16(v.w - __bfloat162float(h3));
    hi.x = (uint32_t)__bfloat16_as_ushort(h0) | ((uint32_t)__bfloat16_as_ushort(h1) << 16);
    hi.y = (uint32_t)__bfloat16_as_ushort(h2) | ((uint32_t)__bfloat16_as_ushort(h3) << 16);
    lo.x = (uint32_t)__bfloat16_as_ushort(l0) | ((uint32_t)__bfloat16_as_ushort(l1) << 16);
    lo.y = (uint32_t)__bfloat16_as_ushort(l2) | ((uint32_t)__bfloat16_as_ushort(l3) << 16);
}

#define LDSM_X4(r0, r1, r2, r3, addr) \
    asm volatile("ldmatrix.sync.aligned.m8n8.x4.shared.b16 {%0,%1,%2,%3}, [%4];" \
                 : "=r"(r0), "=r"(r1), "=r"(r2), "=r"(r3) : "r"(addr))

#define MMA16816(c, a0, a1, a2, a3, b0, b1) \
    asm volatile("mma.sync.aligned.m16n8k16.row.col.f32.bf16.bf16.f32 " \
                 "{%0,%1,%2,%3}, {%4,%5,%6,%7}, {%8,%9}, {%0,%1,%2,%3};" \
                 : "+f"((c)[0]), "+f"((c)[1]), "+f"((c)[2]), "+f"((c)[3]) \
                 : "r"(a0), "r"(a1), "r"(a2), "r"(a3), "r"(b0), "r"(b1))

#define CP_ASYNC16(dst, src) \
    asm volatile("cp.async.ca.shared.global [%0], [%1], 16;" :: "r"(dst), "l"(src) : "memory")
#define CP_COMMIT() asm volatile("cp.async.commit_group;" ::: "memory")

// ---------------- fused zero + weight prepack --------------------------------
static constexpr int ZERO_F4 = 3200000 + 25000;          // agg + deg as float4
static constexpr int ZB = (ZERO_F4 + 1 + 255) / 256;     // 12599

__global__ void zero_prepack_kernel(const float* __restrict__ W1,
                                    const float* __restrict__ W2,
                                    unsigned char* __restrict__ o1h,
                                    unsigned char* __restrict__ o1l,
                                    unsigned char* __restrict__ o2h,
                                    unsigned char* __restrict__ o2l) {
    int b = blockIdx.x;
    if (b < ZB) {
        int i = b * 256 + threadIdx.x;
        const float4 z4 = make_float4(0.f, 0.f, 0.f, 0.f);
        if (i < 3200000)        ((float4*)g_agg)[i] = z4;
        else if (i < ZERO_F4)   ((float4*)g_deg)[i - 3200000] = z4;
        else if (i == ZERO_F4) {
            #pragma unroll
            for (int t = 0; t < N_REL; t++) g_tcur[t] = 0;
        }
        return;
    }
    int t = (b - ZB) * 256 + threadIdx.x;       // 0..65535
    const float* W = (t < 32768) ? W1 : W2;
    unsigned char* oh = (t < 32768) ? o1h : o2h;
    unsigned char* ol = (t < 32768) ? o1l : o2l;
    int u  = t & 32767;
    int r  = u >> 12;
    int j  = (u >> 5) & 127;
    int k  = (u & 31) * 4;
    const float* Wr = W + r * 16384;
    float4 v = make_float4(Wr[(k + 0) * 128 + j], Wr[(k + 1) * 128 + j],
                           Wr[(k + 2) * 128 + j], Wr[(k + 3) * 128 + j]);
    uint2 hi, lo;
    split4(v, hi, lo);
    uint32_t off = (uint32_t)r * 32768u + (uint32_t)j * 256u + (uint32_t)k * 2u;
    *(uint2*)(oh + off) = hi;
    *(uint2*)(ol + off) = lo;
}

// ---------------- degree histogram -------------------------------------------
__global__ void hist_kernel(const int* __restrict__ col) {
    int e = blockIdx.x * 256 + threadIdx.x;
    if (e < N_EDGES) atomicAdd(&g_deg[col[e]], 1.0f);
}

// ---------------- bucket fill (inline norm coefficients) ---------------------
__global__ void fill_kernel(const int* __restrict__ row,
                            const int* __restrict__ col,
                            const int* __restrict__ etype,
                            const float* __restrict__ ew) {
    int e = blockIdx.x * 256 + threadIdx.x;
    if (e >= N_EDGES) return;
    int r = row[e], c = col[e], t = etype[e];
    float dr = g_deg[r], dc = g_deg[c];
    float ir = (dr > 0.0f) ? rsqrtf(dr) : 0.0f;
    float cf = ir * rsqrtf(dc) * ew[e];          // dc >= 1 (this edge targets c)
    int p = atomicAdd(&g_tcur[t], 1);
    int gi = t * BUCKET_STRIDE + p;
    g_erow [gi] = r;
    g_ecol [gi] = c;
    g_ecoef[gi] = cf;
}

// ---------------- edge-batched GEMM: agg[col] += coef * (x[row] @ W_t) -------
// 64-edge full-width tiles, 256 threads, 2 CTAs/SM.
// Single-barrier design: gather -> sync -> MMA -> direct v2-RED from fragments.
static constexpr int S_ELEM = 136;
static constexpr int S_BYTE = S_ELEM * 2;              // 272
static constexpr int A_TILE = TILE_M * S_BYTE;         // 17408
static constexpr int B_TILE = 128 * S_BYTE;            // 34816
static constexpr int OFF_A_HI = 0;
static constexpr int OFF_A_LO = A_TILE;                // 17408
static constexpr int OFF_B_HI = 2 * A_TILE;            // 34816
static constexpr int OFF_B_LO = OFF_B_HI + B_TILE;     // 69632
static constexpr int SMEM_BYTES = OFF_B_LO + B_TILE;   // 104448

__global__ __launch_bounds__(256, 2)
void egemm_kernel(const float* __restrict__ A,
                  const uint4* __restrict__ Bh,
                  const uint4* __restrict__ Bl) {
    extern __shared__ unsigned char smem[];
    const uint32_t sb = smem_u32(smem);
    const int tid    = threadIdx.x;
    const int wid    = tid >> 5;
    const int lane   = tid & 31;
    const int warp_m = wid & 1;          // 2 tiles of 32 rows
    const int warp_n = wid >> 1;         // 4 tiles of 32 cols

    const int t   = blockIdx.y;
    const int cnt = g_tcur[t];
    const int ntiles = (cnt + TILE_M - 1) / TILE_M;
    if ((int)blockIdx.x >= ntiles) return;
    const int ebase = blockIdx.x * TILE_M;
    const int bbase = t * BUCKET_STRIDE;

    // ---- B load (cp.async; W_t prepacked, L2-resident) ---------------------
    {
        uint32_t dstH = sb + OFF_B_HI, dstL = sb + OFF_B_LO;
        const char* srcH = (const char*)Bh + (size_t)t * 32768;
        const char* srcL = (const char*)Bl + (size_t)t * 32768;
        #pragma unroll
        for (int q = 0; q < 8; q++) {
            int i   = tid + q * 256;       // 0..2047 chunks of 16B
            int j   = i >> 4;
            int k16 = i & 15;
            uint32_t doff = (uint32_t)j * S_BYTE + k16 * 16;
            uint32_t soff = (uint32_t)j * 256 + k16 * 16;
            CP_ASYNC16(dstH + doff, srcH + soff);
            CP_ASYNC16(dstL + doff, srcL + soff);
        }
        CP_COMMIT();
    }

    // ---- gather source rows + bf16 hi/lo split (row idx straight from gmem) -
    {
        const int cg    = tid & 31;
        const int rbase = tid >> 5;      // 0..7
        #pragma unroll
        for (int i = 0; i < 8; i++) {
            int row  = rbase + i * 8;
            int gidx = ebase + row;
            int srow = (gidx < cnt) ? g_erow[bbase + gidx] : 0;   // 32-lane bcast
            float4 v = ((const float4*)A)[(size_t)srow * 32 + cg];
            uint2 hi, lo;
            split4(v, hi, lo);
            uint32_t off = (uint32_t)row * S_BYTE + (uint32_t)cg * 8;
            *(uint2*)(smem + OFF_A_HI + off) = hi;
            *(uint2*)(smem + OFF_A_LO + off) = lo;
        }
    }
    asm volatile("cp.async.wait_group 0;" ::: "memory");
    __syncthreads();      // the only CTA barrier

    // ldmatrix fragment addresses
    const int lr = lane & 15;
    const int lc = lane >> 4;
    uint32_t aRow[2], bRow[2];
    #pragma unroll
    for (int mt = 0; mt < 2; mt++)
        aRow[mt] = (uint32_t)(warp_m * 32 + mt * 16 + lr) * S_BYTE + lc * 16;
    #pragma unroll
    for (int g = 0; g < 2; g++)
        bRow[g] = (uint32_t)(warp_n * 32 + g * 16 + lr) * S_BYTE + lc * 16;

    float c[2][4][4];
    #pragma unroll
    for (int mt = 0; mt < 2; mt++)
        #pragma unroll
        for (int nt = 0; nt < 4; nt++)
            #pragma unroll
            for (int e = 0; e < 4; e++) c[mt][nt][e] = 0.0f;

    const uint32_t bStageH = sb + OFF_B_HI;
    const uint32_t bStageL = sb + OFF_B_LO;
    const uint32_t aBaseH  = sb + OFF_A_HI;
    const uint32_t aBaseL  = sb + OFF_A_LO;

    uint32_t ah[2][2][4], al[2][2][4], bh[2][2][4], bl[2][2][4];

    #define LOAD_FRAG(buf, kb)                                                   \
        do {                                                                     \
            _Pragma("unroll")                                                    \
            for (int mt = 0; mt < 2; mt++) {                                     \
                LDSM_X4(ah[buf][mt][0], ah[buf][mt][1], ah[buf][mt][2],          \
                        ah[buf][mt][3], aBaseH + aRow[mt] + (kb));               \
                LDSM_X4(al[buf][mt][0], al[buf][mt][1], al[buf][mt][2],          \
                        al[buf][mt][3], aBaseL + aRow[mt] + (kb));               \
            }                                                                    \
            _Pragma("unroll")                                                    \
            for (int g = 0; g < 2; g++) {                                        \
                LDSM_X4(bh[buf][g][0], bh[buf][g][1], bh[buf][g][2],             \
                        bh[buf][g][3], bStageH + bRow[g] + (kb));                \
                LDSM_X4(bl[buf][g][0], bl[buf][g][1], bl[buf][g][2],             \
                        bl[buf][g][3], bStageL + bRow[g] + (kb));                \
            }                                                                    \
        } while (0)

    LOAD_FRAG(0, 0);
    #pragma unroll
    for (int ks = 0; ks < 8; ks++) {
        const int cur = ks & 1;
        if (ks < 7) LOAD_FRAG(cur ^ 1, (ks + 1) * 32);
        // c += Ah@Bh + Ah@Bl + Al@Bh (Al@Bl dropped, ~2^-18 relative)
        #pragma unroll
        for (int mt = 0; mt < 2; mt++)
            #pragma unroll
            for (int g = 0; g < 2; g++) {
                MMA16816(c[mt][g * 2 + 0], ah[cur][mt][0], ah[cur][mt][1],
                         ah[cur][mt][2], ah[cur][mt][3], bh[cur][g][0], bh[cur][g][2]);
                MMA16816(c[mt][g * 2 + 1], ah[cur][mt][0], ah[cur][mt][1],
                         ah[cur][mt][2], ah[cur][mt][3], bh[cur][g][1], bh[cur][g][3]);
                MMA16816(c[mt][g * 2 + 0], ah[cur][mt][0], ah[cur][mt][1],
                         ah[cur][mt][2], ah[cur][mt][3], bl[cur][g][0], bl[cur][g][2]);
                MMA16816(c[mt][g * 2 + 1], ah[cur][mt][0], ah[cur][mt][1],
                         ah[cur][mt][2], ah[cur][mt][3], bl[cur][g][1], bl[cur][g][3]);
                MMA16816(c[mt][g * 2 + 0], al[cur][mt][0], al[cur][mt][1],
                         al[cur][mt][2], al[cur][mt][3], bh[cur][g][0], bh[cur][g][2]);
                MMA16816(c[mt][g * 2 + 1], al[cur][mt][0], al[cur][mt][1],
                         al[cur][mt][2], al[cur][mt][3], bh[cur][g][1], bh[cur][g][3]);
            }
    }
    #undef LOAD_FRAG

    // ---- direct v2-RED epilogue (no stage, no barrier) ----------------------
    // fragment (mt, nt) lanes: rows rA = warp_m*32+mt*16+gid, rB = rA+8;
    // cols d = warp_n*32 + nt*8 + 2*tig  (values c[0],c[1] row rA; c[2],c[3] row rB)
    const int gid = lane >> 2;
    const int tig = lane & 3;
    #pragma unroll
    for (int mt = 0; mt < 2; mt++) {
        #pragma unroll
        for (int half = 0; half < 2; half++) {
            int row  = warp_m * 32 + mt * 16 + gid + half * 8;
            int gidx = ebase + row;
            if (gidx < cnt) {
                float cf = g_ecoef[bbase + gidx];    // 4-lane broadcast
                int   cn = g_ecol [bbase + gidx];
                if (cf != 0.0f) {
                    float* base = &g_agg[(size_t)cn * DIM + warp_n * 32 + 2 * tig];
                    const int o = half * 2;
                    #pragma unroll
                    for (int nt = 0; nt < 4; nt++) {
                        asm volatile("red.global.add.v2.f32 [%0], {%1, %2};"
                                     :: "l"(base + nt * 8),
                                        "f"(cf * c[mt][nt][o]), "f"(cf * c[mt][nt][o + 1])
                                     : "memory");
                    }
                }
            }
        }
    }
}

// ---------------- bias + relu -> z1, re-zero agg for conv2 --------------------
__global__ void bias_relu_zero_kernel(const float* __restrict__ b1) {
    int i = blockIdx.x * blockDim.x + threadIdx.x;       // float4 index
    if (i < N_NODES * DIM / 4) {
        float4 a = ((const float4*)g_agg)[i];
        const float4 b = ((const float4*)b1)[i & 31];
        float4 o;
        o.x = fmaxf(a.x + b.x, 0.f);
        o.y = fmaxf(a.y + b.y, 0.f);
        o.z = fmaxf(a.z + b.z, 0.f);
        o.w = fmaxf(a.w + b.w, 0.f);
        ((float4*)g_z1)[i] = o;
        ((float4*)g_agg)[i] = make_float4(0.f, 0.f, 0.f, 0.f);
    }
}

// ---------------- final combine ----------------------------------------------
__global__ void final_kernel(const float* __restrict__ x,
                             const float* __restrict__ b2,
                             float* __restrict__ out) {
    int i = blockIdx.x * blockDim.x + threadIdx.x;       // float4 index
    if (i < N_NODES * DIM / 4) {
        float4 a  = ((const float4*)g_agg)[i];
        float4 b  = ((const float4*)b2)[i & 31];
        float4 z1 = ((const float4*)g_z1)[i];
        float4 xv = ((const float4*)x)[i];
        float4 st, sh;
        st.x = (xv.x + z1.x + a.x + b.x) * 0.25f;  sh.x = (z1.x + a.x + b.x) * (1.f / 3.f);
        st.y = (xv.y + z1.y + a.y + b.y) * 0.25f;  sh.y = (z1.y + a.y + b.y) * (1.f / 3.f);
        st.z = (xv.z + z1.z + a.z + b.z) * 0.25f;  sh.z = (z1.z + a.z + b.z) * (1.f / 3.f);
        st.w = (xv.w + z1.w + a.w + b.w) * 0.25f;  sh.w = (z1.w + a.w + b.w) * (1.f / 3.f);
        ((float4*)out)[i] = st;
        ((float4*)out)[(size_t)N_NODES * DIM / 4 + i] = sh;
    }
}

// ---------------- launch -----------------------------------------------------
extern "C" void kernel_launch(void* const* d_in, const int* in_sizes, int n_in,
                              void* d_out, int out_size) {
    const float* x  = (const float*)d_in[0];
    const int*   ei = (const int*)  d_in[1];
    const int*   et = (const int*)  d_in[2];
    const float* ew = (const float*)d_in[3];
    const float* W1 = (const float*)d_in[4];
    const float* b1 = (const float*)d_in[5];
    const float* W2 = (const float*)d_in[6];
    const float* b2 = (const float*)d_in[7];
    float* out = (float*)d_out;

    const int* row = ei;
    const int* col = ei + N_EDGES;

    void *p_z1, *p_B1h, *p_B1l, *p_B2h, *p_B2l;
    cudaGetSymbolAddress(&p_z1,  g_z1);
    cudaGetSymbolAddress(&p_B1h, g_B1h);
    cudaGetSymbolAddress(&p_B1l, g_B1l);
    cudaGetSymbolAddress(&p_B2h, g_B2h);
    cudaGetSymbolAddress(&p_B2l, g_B2l);

    cudaFuncSetAttribute(egemm_kernel, cudaFuncAttributeMaxDynamicSharedMemorySize, SMEM_BYTES);

    const int EB = (N_EDGES + 255) / 256;
    const int V4 = (N_NODES * DIM / 4 + 255) / 256;
    dim3 egrid(MAX_TILES_PER_TYPE, N_REL);

    zero_prepack_kernel<<<ZB + 256, 256>>>(W1, W2,
                                 (unsigned char*)p_B1h, (unsigned char*)p_B1l,
                                 (unsigned char*)p_B2h, (unsigned char*)p_B2l); // [0]
    hist_kernel<<<EB, 256>>>(col);                                         // [1]
    fill_kernel<<<EB, 256>>>(row, col, et, ew);                            // [2]

    // conv 1: agg += coef * (x[row] @ W1[t]) scattered to col
    egemm_kernel<<<egrid, 256, SMEM_BYTES>>>(x, (const uint4*)p_B1h,
                                             (const uint4*)p_B1l);         // [3] <- ncu
    bias_relu_zero_kernel<<<V4, 256>>>(b1);                                // [4]

    // conv 2: agg += coef * (z1[row] @ W2[t]) scattered to col
    egemm_kernel<<<egrid, 256, SMEM_BYTES>>>((const float*)p_z1,
                                             (const uint4*)p_B2h,
                                             (const uint4*)p_B2l);         // [5]
    final_kernel<<<V4, 256>>>(x, b2, out);                                 // [6]
}